// round 17
// baseline (speedup 1.0000x reference)
#include <cuda_runtime.h>
#include <cuda_fp16.h>
#include <cstdint>
#include <cstddef>

// Shapes (fixed)
#define NB 16
#define NM 128
#define NH 256
#define NE 128
#define NC 384
#define NROWS 2048
#define EDGE_GRID 148

// Scratch
__device__ half  g_msgH[NROWS * NC];   // [2048][384]: msg_x | msg_e (fp16)
__device__ half  g_tH[NROWS * NH];
__device__ half  g_uH[NROWS * NH];
// chunk-blocked fp16 operands: [kc][n=256][k=32], each 16KB chunk contiguous
__device__ half  g_WrB[12 * 256 * 32];
__device__ half  g_W0B[8 * 256 * 32];
__device__ half  g_W1B[8 * 256 * 32];
__device__ half  g_XB[NB * 4 * 256 * 32];

// ---------------------------------------------------------------------------
// helpers
// ---------------------------------------------------------------------------
__device__ __forceinline__ uint32_t h2u(half2 h) {
    return *reinterpret_cast<uint32_t*>(&h);
}
__device__ __forceinline__ uint2 f4toh4(float4 v) {
    return make_uint2(h2u(__floats2half2_rn(v.x, v.y)),
                      h2u(__floats2half2_rn(v.z, v.w)));
}
__device__ __forceinline__ void mma16h(float* d, const uint32_t* a, const uint32_t* b) {
    asm volatile(
        "mma.sync.aligned.m16n8k16.row.col.f32.f16.f16.f32 "
        "{%0,%1,%2,%3}, {%4,%5,%6,%7}, {%8,%9}, {%0,%1,%2,%3};"
        : "+f"(d[0]), "+f"(d[1]), "+f"(d[2]), "+f"(d[3])
        : "r"(a[0]), "r"(a[1]), "r"(a[2]), "r"(a[3]),
          "r"(b[0]), "r"(b[1]));
}

// ---------------------------------------------------------------------------
// cvt kernel (VERBATIM R14): W / X_b -> blocked fp16 [kc][256][32]
// ---------------------------------------------------------------------------
__global__ __launch_bounds__(256)
void cvt_blocked(const float* __restrict__ Wr, const float* __restrict__ W0,
                 const float* __restrict__ W1, const float* __restrict__ X)
{
    __shared__ float tile[32][33];
    const int id = blockIdx.x;
    const float* src; half* dst; int kc, n0;
    if (id < 96)       { kc = id >> 3; n0 = (id & 7) * 32; src = Wr; dst = g_WrB; }
    else if (id < 160) { int t = id - 96;  kc = t >> 3; n0 = (t & 7) * 32;
                         src = W0; dst = g_W0B; }
    else if (id < 224) { int t = id - 160; kc = t >> 3; n0 = (t & 7) * 32;
                         src = W1; dst = g_W1B; }
    else {
        int t = id - 224;
        int b = t >> 5, tt = t & 31;
        kc = tt >> 3; n0 = (tt & 7) * 32;
        src = X + (size_t)b * 32768;
        dst = g_XB + (size_t)b * 32768;
    }
    const int c = threadIdx.x & 31, r8 = threadIdx.x >> 5;
    #pragma unroll
    for (int p = 0; p < 4; ++p) {
        int r = r8 + p * 8;
        tile[r][c] = src[(size_t)(kc * 32 + r) * 256 + n0 + c];
    }
    __syncthreads();
    const int nl = threadIdx.x >> 3, kl0 = (threadIdx.x & 7) * 4;
    half* o = dst + ((size_t)(kc * 256 + n0 + nl) * 32 + kl0);
    half2 h0 = __floats2half2_rn(tile[kl0][nl],     tile[kl0 + 1][nl]);
    half2 h1 = __floats2half2_rn(tile[kl0 + 2][nl], tile[kl0 + 3][nl]);
    *(uint2*)o = make_uint2(h2u(h0), h2u(h1));
}

// ---------------------------------------------------------------------------
// Edge kernel (R15 structure; msg_e written as fp16 into g_msgH)
// ---------------------------------------------------------------------------
#define EH_PITCH 136
#define ES_HALF  (128 * EH_PITCH)
#define ES_OFF   0
#define WS_OFF   69632
#define AW_OFF   104448
#define RED_OFF  105472
#define SM_BYTES 107520

__device__ __forceinline__ void compute_quarter_h(const half* __restrict__ ap,
                                                  const half* __restrict__ bp,
                                                  float acc[2][4][4])
{
    #pragma unroll
    for (int ss = 0; ss < 2; ++ss) {
        const int kb = ss * 16;
        uint32_t a[2][4];
        #pragma unroll
        for (int m = 0; m < 2; ++m) {
            const half* p = ap + m * (16 * EH_PITCH) + kb;
            a[m][0] = *(const uint32_t*)(p);
            a[m][1] = *(const uint32_t*)(p + 8 * EH_PITCH);
            a[m][2] = *(const uint32_t*)(p + 8);
            a[m][3] = *(const uint32_t*)(p + 8 * EH_PITCH + 8);
        }
        uint32_t bq[4][2];
        #pragma unroll
        for (int n = 0; n < 4; ++n) {
            const half* p = bp + n * (8 * EH_PITCH) + kb;
            bq[n][0] = *(const uint32_t*)(p);
            bq[n][1] = *(const uint32_t*)(p + 8);
        }
        #pragma unroll
        for (int m = 0; m < 2; ++m)
            #pragma unroll
            for (int n = 0; n < 4; ++n)
                mma16h(acc[m][n], a[m], bq[n]);
    }
}

__global__ __launch_bounds__(512, 1)
void edge_msg_mma(const float* __restrict__ E,
                  const float* __restrict__ A,
                  const float* __restrict__ We,
                  const float* __restrict__ be,
                  half* __restrict__ msgH)
{
    extern __shared__ char smc[];
    half*  Es  = (half*)(smc + ES_OFF);
    half*  Ws  = (half*)(smc + WS_OFF);
    float* awb = (float*)(smc + AW_OFF);
    float* red = (float*)(smc + RED_OFF);

    const int tid  = threadIdx.x;
    const int lane = tid & 31;
    const int wid  = tid >> 5;
    const int rg   = wid >> 2;
    const int cg   = wid & 3;
    const int row0 = rg * 32;
    const int col0 = cg * 32;

    float be0[4], be1[4];
    #pragma unroll
    for (int n = 0; n < 4; ++n) {
        be0[n] = be[col0 + 8 * n + 2 * (lane & 3)];
        be1[n] = be[col0 + 8 * n + 2 * (lane & 3) + 1];
    }

    for (int idx = tid; idx < 8192; idx += 512) {
        int f = idx & 127;
        int e = (idx >> 7) * 2;
        *(half2*)(Ws + f * EH_PITCH + e) =
            __floats2half2_rn(We[(size_t)e * 128 + f], We[(size_t)(e + 1) * 128 + f]);
    }

    const int t0  = blockIdx.x;
    const int ntl = (NROWS - t0 + EDGE_GRID - 1) / EDGE_GRID;

    const int ech = (tid & 7) * 4;
    const int ir0 = tid >> 3;
    auto ldt = [&](float4* r, int t) {
        const float* src = E + (size_t)(t >> 7) * 2097152
                             + (size_t)ir0 * 16384
                             + (size_t)(t & 127) * 128 + ech;
        #pragma unroll
        for (int q = 0; q < 4; ++q) {
            r[2 * q]     = *(const float4*)(src + q * 32);
            r[2 * q + 1] = *(const float4*)(src + q * 32 + (size_t)64 * 16384);
        }
    };
    auto stg = [&](const float4* r, half* base) {
        half* qd0 = base + ir0 * EH_PITCH + ech;
        #pragma unroll
        for (int q = 0; q < 4; ++q) {
            *(uint2*)(qd0 + q * 32)                 = f4toh4(r[2 * q]);
            *(uint2*)(qd0 + q * 32 + 64 * EH_PITCH) = f4toh4(r[2 * q + 1]);
        }
    };

    float4 pre[8];
    ldt(pre, t0);
    stg(pre, Es);
    if (tid < 128)
        awb[tid] = A[(size_t)(t0 >> 7) * 16384 + (size_t)tid * 128 + (t0 & 127)];
    float awreg = 0.f;
    if (ntl > 1) {
        const int t1 = t0 + EDGE_GRID;
        ldt(pre, t1);
        if (tid < 128)
            awreg = A[(size_t)(t1 >> 7) * 16384 + (size_t)tid * 128 + (t1 & 127)];
    }

    float acc[2][4][4];
    #pragma unroll
    for (int m = 0; m < 2; ++m)
        #pragma unroll
        for (int n = 0; n < 4; ++n)
            #pragma unroll
            for (int q = 0; q < 4; ++q) acc[m][n][q] = 0.f;

    const half* aptr0 = Es + (row0 + (lane >> 2)) * EH_PITCH + (lane & 3) * 2;
    const half* bptr  = Ws + (col0 + (lane >> 2)) * EH_PITCH + (lane & 3) * 2;

    for (int k = 0; k < ntl; ++k) {
        const int t = t0 + k * EDGE_GRID;
        __syncthreads();

        if (k + 1 < ntl) {
            if (tid < 128) awb[((k + 1) & 1) * 128 + tid] = awreg;
            stg(pre, Es + ((k + 1) & 1) * ES_HALF);
            if (k + 2 < ntl) {
                const int t2 = t0 + (k + 2) * EDGE_GRID;
                ldt(pre, t2);
                if (tid < 128)
                    awreg = A[(size_t)(t2 >> 7) * 16384 + (size_t)tid * 128 + (t2 & 127)];
            }
        }

        const half* ap = aptr0 + (k & 1) * ES_HALF;
        #pragma unroll
        for (int q = 0; q < 4; ++q)
            compute_quarter_h(ap + q * 32, bptr + q * 32, acc);

        // ---- epilogue ----
        {
            const float* aw = awb + (k & 1) * 128;
            float p0[4], p1[4];
            #pragma unroll
            for (int n = 0; n < 4; ++n) { p0[n] = 0.f; p1[n] = 0.f; }
            #pragma unroll
            for (int m = 0; m < 2; ++m) {
                float w0 = aw[row0 + 16 * m + (lane >> 2)];
                float w1 = aw[row0 + 16 * m + (lane >> 2) + 8];
                #pragma unroll
                for (int n = 0; n < 4; ++n) {
                    p0[n] += w0 * fmaxf(acc[m][n][0] + be0[n], 0.f)
                           + w1 * fmaxf(acc[m][n][2] + be0[n], 0.f);
                    p1[n] += w0 * fmaxf(acc[m][n][1] + be1[n], 0.f)
                           + w1 * fmaxf(acc[m][n][3] + be1[n], 0.f);
                    acc[m][n][0] = 0.f; acc[m][n][1] = 0.f;
                    acc[m][n][2] = 0.f; acc[m][n][3] = 0.f;
                }
            }
            #pragma unroll
            for (int off = 4; off < 32; off <<= 1) {
                #pragma unroll
                for (int n = 0; n < 4; ++n) {
                    p0[n] += __shfl_xor_sync(0xffffffffu, p0[n], off);
                    p1[n] += __shfl_xor_sync(0xffffffffu, p1[n], off);
                }
            }
            if (rg > 0 && lane < 4) {
                #pragma unroll
                for (int n = 0; n < 4; ++n) {
                    int f = col0 + 8 * n + 2 * lane;
                    red[(rg - 1) * 128 + f]     = p0[n];
                    red[(rg - 1) * 128 + f + 1] = p1[n];
                }
            }
            __syncthreads();
            if (rg == 0 && lane < 4) {
                #pragma unroll
                for (int n = 0; n < 4; ++n) {
                    int f = col0 + 8 * n + 2 * lane;
                    float v0 = p0[n] + red[f] + red[128 + f] + red[256 + f];
                    float v1 = p1[n] + red[f + 1] + red[128 + f + 1] + red[256 + f + 1];
                    *(half2*)(msgH + (size_t)t * NC + NH + f) =
                        __floats2half2_rn(v0, v1);
                }
            }
        }
    }
}

// ---------------------------------------------------------------------------
// msgx kernel: msg_x = AsT @ X_b -> g_msgH cols 0..255 (fp16).
// ---------------------------------------------------------------------------
#define AST_P 136
#define BS_P  40

__device__ __forceinline__ void fgemm_h(const half* __restrict__ Asm, int PA,
                                        const half* __restrict__ WB,
                                        half* __restrict__ bs0,
                                        half* __restrict__ bs1,
                                        int nch, int tid, int lane, int wcol0,
                                        float acc[4][4])
{
    const half* wsrc = WB + (size_t)tid * 32;
    uint4 pw0[4], pw1[4];
    #pragma unroll
    for (int q = 0; q < 4; ++q) pw0[q] = *(const uint4*)(wsrc + q * 8);
    if (nch > 1) {
        #pragma unroll
        for (int q = 0; q < 4; ++q) pw1[q] = *(const uint4*)(wsrc + 8192 + q * 8);
    }

    const half* apb = Asm + (lane >> 2) * PA + (lane & 3) * 2;

    for (int kc = 0; kc < nch; ++kc) {
        half* bd = ((kc & 1) ? bs1 : bs0) + tid * BS_P;
        #pragma unroll
        for (int q = 0; q < 4; ++q) *(uint4*)(bd + q * 8) = pw0[q];
        #pragma unroll
        for (int q = 0; q < 4; ++q) pw0[q] = pw1[q];
        if (kc + 2 < nch) {
            const half* ws = wsrc + (size_t)(kc + 2) * 8192;
            #pragma unroll
            for (int q = 0; q < 4; ++q) pw1[q] = *(const uint4*)(ws + q * 8);
        }
        __syncthreads();

        const half* bp = ((kc & 1) ? bs1 : bs0)
                       + (wcol0 + (lane >> 2)) * BS_P + (lane & 3) * 2;
        const half* ap = apb + kc * 32;
        #pragma unroll
        for (int ss = 0; ss < 2; ++ss) {
            const half* pa = ap + ss * 16;
            uint32_t a[4];
            a[0] = *(const uint32_t*)(pa);
            a[1] = *(const uint32_t*)(pa + 8 * PA);
            a[2] = *(const uint32_t*)(pa + 8);
            a[3] = *(const uint32_t*)(pa + 8 * PA + 8);
            uint32_t bq[4][2];
            #pragma unroll
            for (int n = 0; n < 4; ++n) {
                const half* pb = bp + n * (8 * BS_P) + ss * 16;
                bq[n][0] = *(const uint32_t*)(pb);
                bq[n][1] = *(const uint32_t*)(pb + 8);
            }
            #pragma unroll
            for (int n = 0; n < 4; ++n) mma16h(acc[n], a, bq[n]);
        }
    }
}

__global__ __launch_bounds__(256)
void msgx_gemm(const float* __restrict__ A, half* __restrict__ msgH)
{
    __shared__ half AsT[16 * AST_P];
    __shared__ half Bs0[256 * BS_P];
    __shared__ half Bs1[256 * BS_P];

    const int r0   = blockIdx.x * 16;
    const int b    = r0 >> 7;
    const int j0   = r0 & 127;
    const int tid  = threadIdx.x;
    const int lane = tid & 31;
    const int wid  = tid >> 5;
    const int wcol0 = wid * 32;

    for (int idx = tid; idx < 2048; idx += 256) {
        int i = idx >> 4, jj = idx & 15;
        AsT[jj * AST_P + i] =
            __float2half(A[(size_t)b * 16384 + (size_t)i * 128 + j0 + jj]);
    }
    __syncthreads();

    float acc[4][4];
    #pragma unroll
    for (int n = 0; n < 4; ++n)
        #pragma unroll
        for (int q = 0; q < 4; ++q) acc[n][q] = 0.f;

    fgemm_h(AsT, AST_P, g_XB + (size_t)b * 32768, Bs0, Bs1,
            4, tid, lane, wcol0, acc);

    const int erow = lane >> 2;
    const int ecol = 2 * (lane & 3);
    #pragma unroll
    for (int n = 0; n < 4; ++n) {
        int col = wcol0 + 8 * n + ecol;
        *(half2*)(msgH + (size_t)(r0 + erow) * NC + col) =
            __floats2half2_rn(acc[n][0], acc[n][1]);
        *(half2*)(msgH + (size_t)(r0 + erow + 8) * NC + col) =
            __floats2half2_rn(acc[n][2], acc[n][3]);
    }
}

// ---------------------------------------------------------------------------
// Layer GEMM: Out[2048][256] = epi(In[2048][K] @ W[K][256]).
// grid (128, 4) = 512 CTAs, 128 thr = 4 warps, warp tile 16x16.
// ---------------------------------------------------------------------------
template <int K, int RESID, int OUTF32>
__global__ __launch_bounds__(128)
void gemm_layer(const half* __restrict__ In,
                const half* __restrict__ WB,
                const float* __restrict__ bias,
                const float* __restrict__ Xres,
                const float* __restrict__ epsp,
                half* __restrict__ OutH,
                float* __restrict__ OutF)
{
    constexpr int PA  = K + 8;
    constexpr int NCH = K / 32;
    __shared__ half As[16 * PA];
    __shared__ half Bs[2][64 * BS_P];

    const int r0  = blockIdx.x * 16;
    const int c0  = blockIdx.y * 64;
    const int tid  = threadIdx.x;
    const int lane = tid & 31;
    const int wid  = tid >> 5;
    const int wcol0 = wid * 16;

    {
        const int row = tid >> 3;
        const half* src = In + (size_t)(r0 + row) * K + (tid & 7) * 8;
        half* dst = As + row * PA + (tid & 7) * 8;
        #pragma unroll
        for (int q = 0; q < K / 64; ++q)
            *(uint4*)(dst + q * 64) = *(const uint4*)(src + q * 64);
    }

    const half* wsrc = WB + ((size_t)(c0 + (tid >> 1)) * 32 + (tid & 1) * 16);
    uint4 pw[2];
    pw[0] = *(const uint4*)(wsrc);
    pw[1] = *(const uint4*)(wsrc + 8);

    float acc[2][4];
    #pragma unroll
    for (int n = 0; n < 2; ++n)
        #pragma unroll
        for (int q = 0; q < 4; ++q) acc[n][q] = 0.f;

    const half* apb = As + (lane >> 2) * PA + (lane & 3) * 2;

    for (int kc = 0; kc < NCH; ++kc) {
        half* bd = Bs[kc & 1] + (tid >> 1) * BS_P + (tid & 1) * 16;
        *(uint4*)(bd)     = pw[0];
        *(uint4*)(bd + 8) = pw[1];
        if (kc + 1 < NCH) {
            const half* ws = wsrc + (size_t)(kc + 1) * 8192;
            pw[0] = *(const uint4*)(ws);
            pw[1] = *(const uint4*)(ws + 8);
        }
        __syncthreads();

        const half* bp = Bs[kc & 1] + (wcol0 + (lane >> 2)) * BS_P + (lane & 3) * 2;
        const half* ap = apb + kc * 32;
        #pragma unroll
        for (int ss = 0; ss < 2; ++ss) {
            const half* pa = ap + ss * 16;
            uint32_t a[4];
            a[0] = *(const uint32_t*)(pa);
            a[1] = *(const uint32_t*)(pa + 8 * PA);
            a[2] = *(const uint32_t*)(pa + 8);
            a[3] = *(const uint32_t*)(pa + 8 * PA + 8);
            uint32_t bq[2][2];
            #pragma unroll
            for (int n = 0; n < 2; ++n) {
                const half* pb = bp + n * (8 * BS_P) + ss * 16;
                bq[n][0] = *(const uint32_t*)(pb);
                bq[n][1] = *(const uint32_t*)(pb + 8);
            }
            #pragma unroll
            for (int n = 0; n < 2; ++n) mma16h(acc[n], a, bq[n]);
        }
    }

    const int erow = lane >> 2;
    const int ecol = 2 * (lane & 3);
    float epsv = 0.f;
    if (RESID) epsv = 1.f + *epsp;

    #pragma unroll
    for (int n = 0; n < 2; ++n) {
        int col = c0 + wcol0 + 8 * n + ecol;
        int r1 = r0 + erow, r2 = r1 + 8;
        float v00 = fmaxf(acc[n][0] + bias[col], 0.f);
        float v01 = fmaxf(acc[n][1] + bias[col + 1], 0.f);
        float v10 = fmaxf(acc[n][2] + bias[col], 0.f);
        float v11 = fmaxf(acc[n][3] + bias[col + 1], 0.f);
        if (RESID) {
            float2 x0 = *(const float2*)(Xres + (size_t)r1 * 256 + col);
            float2 x1 = *(const float2*)(Xres + (size_t)r2 * 256 + col);
            v00 += epsv * x0.x; v01 += epsv * x0.y;
            v10 += epsv * x1.x; v11 += epsv * x1.y;
        }
        if (OUTF32) {
            *(float2*)(OutF + (size_t)r1 * 256 + col) = make_float2(v00, v01);
            *(float2*)(OutF + (size_t)r2 * 256 + col) = make_float2(v10, v11);
        } else {
            *(half2*)(OutH + (size_t)r1 * 256 + col) = __floats2half2_rn(v00, v01);
            *(half2*)(OutH + (size_t)r2 * 256 + col) = __floats2half2_rn(v10, v11);
        }
    }
}

// ---------------------------------------------------------------------------
extern "C" void kernel_launch(void* const* d_in, const int* in_sizes, int n_in,
                              void* d_out, int out_size)
{
    const float* X   = (const float*)d_in[0];
    const float* E   = (const float*)d_in[1];
    const float* A   = (const float*)d_in[2];
    const float* eps = (const float*)d_in[3];
    const float* We  = (const float*)d_in[4];
    const float* be  = (const float*)d_in[5];
    const float* Wr  = (const float*)d_in[6];
    const float* br  = (const float*)d_in[7];
    const float* W0  = (const float*)d_in[8];
    const float* b0  = (const float*)d_in[9];
    const float* W1  = (const float*)d_in[10];
    const float* b1  = (const float*)d_in[11];
    float* out = (float*)d_out;

    // Device addresses of ALL __device__ globals passed as kernel args
    void *pmsg, *pt, *pu, *pwr, *pw0, *pw1;
    cudaGetSymbolAddress(&pmsg, g_msgH);
    cudaGetSymbolAddress(&pt,  g_tH);
    cudaGetSymbolAddress(&pu,  g_uH);
    cudaGetSymbolAddress(&pwr, g_WrB);
    cudaGetSymbolAddress(&pw0, g_W0B);
    cudaGetSymbolAddress(&pw1, g_W1B);
    half* msgH = (half*)pmsg;
    half* tH   = (half*)pt;
    half* uH   = (half*)pu;
    half* WrB  = (half*)pwr;
    half* W0B  = (half*)pw0;
    half* W1B  = (half*)pw1;

    cudaFuncSetAttribute(edge_msg_mma,
                         cudaFuncAttributeMaxDynamicSharedMemorySize, SM_BYTES);

    cvt_blocked<<<736, 256>>>(Wr, W0, W1, X);
    msgx_gemm<<<128, 256>>>(A, msgH);
    edge_msg_mma<<<EDGE_GRID, 512, SM_BYTES>>>(E, A, We, be, msgH);
    gemm_layer<NC, 1, 0><<<dim3(128, 4), 128>>>(msgH, WrB, br, X, eps, tH, nullptr);
    gemm_layer<NH, 0, 0><<<dim3(128, 4), 128>>>(tH, W0B, b0, nullptr, nullptr, uH, nullptr);
    gemm_layer<NH, 0, 1><<<dim3(128, 4), 128>>>(uH, W1B, b1, nullptr, nullptr, nullptr, out);
}